// round 15
// baseline (speedup 1.0000x reference)
#include <cuda_runtime.h>
#include <cuda_fp16.h>
#include <cstdint>

#define DINLINE __device__ __forceinline__

// ---------------- device scratch (no dynamic alloc allowed) ----------------
static __device__ __align__(16) __half g_xh[8192 * 1024];
static __device__ __align__(16) __half g_fh[3072 * 1024];
static __device__ unsigned g_done = 0;     // prep blocks completed
static __device__ unsigned g_passed = 0;   // gemm blocks completed (for reset)

// ---------------- portable PTX helpers (sm_80-class ISA only) ----------------
DINLINE uint32_t smem_u32(const void* p) {
    uint32_t a;
    asm("{ .reg .u64 t; cvta.to.shared.u64 t, %1; cvt.u32.u64 %0, t; }" : "=r"(a) : "l"(p));
    return a;
}
DINLINE void cp_async16(uint32_t dst, const void* src) {
    asm volatile("cp.async.cg.shared.global [%0], [%1], 16;" :: "r"(dst), "l"(src) : "memory");
}
DINLINE void cp_commit() { asm volatile("cp.async.commit_group;" ::: "memory"); }
DINLINE void cp_wait0() { asm volatile("cp.async.wait_group 0;" ::: "memory"); }
DINLINE void cp_wait1() { asm volatile("cp.async.wait_group 1;" ::: "memory"); }

DINLINE void ldsm4(uint32_t* r, uint32_t addr) {
    asm volatile("ldmatrix.sync.aligned.m8n8.x4.shared.b16 {%0,%1,%2,%3}, [%4];"
                 : "=r"(r[0]), "=r"(r[1]), "=r"(r[2]), "=r"(r[3]) : "r"(addr));
}
DINLINE void mma_f16(float* c, const uint32_t* a, const uint32_t* b) {
    asm volatile(
        "mma.sync.aligned.m16n8k16.row.col.f32.f16.f16.f32 "
        "{%0,%1,%2,%3}, {%4,%5,%6,%7}, {%8,%9}, {%0,%1,%2,%3};"
        : "+f"(c[0]), "+f"(c[1]), "+f"(c[2]), "+f"(c[3])
        : "r"(a[0]), "r"(a[1]), "r"(a[2]), "r"(a[3]), "r"(b[0]), "r"(b[1]));
}

DINLINE uint32_t pack_h2(__half a, __half b) {
    __half2 t = __halves2half2(a, b);
    return *reinterpret_cast<uint32_t*>(&t);
}

// XOR swizzle on 128B rows: 16B-chunk c' = c ^ (row & 7)
DINLINE uint32_t swz(int row, int chunk) {
    return (uint32_t)(row * 128 + (chunk ^ (row & 7)) * 16);
}

// ---------------- grid layout ----------------
static constexpr int N_CVT  = 2048;                  // x convert blocks
static constexpr int N_ROT  = 192;                   // rotate blocks (24 o-tiles x 8 r)
static constexpr int N_PREP = N_CVT + N_ROT;         // 2240
static constexpr int N_GEMM = 64 * 24;               // 1536
static constexpr int GRID   = N_PREP + N_GEMM;       // 3776

static constexpr int BM = 128, BN = 128, BK = 64;
static constexpr int NCHUNKS = 1024 / BK;            // 16
static constexpr int STAGE_BYTES = 32768;
static constexpr int SMEM_SIZE = 3 * STAGE_BYTES;    // 96KB -> 2 CTAs/SM

DINLINE void load_stage(uint32_t sbase, int m0, int n0, int k0, int tid) {
#pragma unroll
    for (int t = 0; t < 16; t++) {
        int idx = tid + t * 128;
        int arr = idx >> 10;         // 0:A 1:B
        int rem = idx & 1023;
        int row = rem >> 3, chunk = rem & 7;
        const __half* src = (arr == 0)
            ? g_xh + (size_t)(m0 + row) * 1024 + k0 + chunk * 8
            : g_fh + (size_t)(n0 + row) * 1024 + k0 + chunk * 8;
        cp_async16(sbase + arr * 16384 + swz(row, chunk), src);
    }
}

// ==================== fused kernel ====================
// bids [0, 2048):      convert x -> fp16 into g_xh (8 float4/thread)
// bids [2048, 2240):   rotate W -> filt via HMMA into g_fh
// bids [2240, 3776):   GEMM out = Xh*Fh^T + bias (gated on prep completion)
__global__ void __launch_bounds__(128, 2) fused_kernel(
    const float4* __restrict__ x4, const float* __restrict__ W,
    const float* __restrict__ qR, const float* __restrict__ kR,
    const float* __restrict__ vR,
    const float* __restrict__ bias, float* __restrict__ out) {
    extern __shared__ __align__(128) char smem[];
    uint32_t sm0 = smem_u32(smem);
    int tid = threadIdx.x;
    int bid = blockIdx.x;

    // ================= path 1: convert x =================
    if (bid < N_CVT) {
        size_t base = (size_t)bid * 1024 + tid;
#pragma unroll
        for (int t = 0; t < 8; t++) {
            size_t i = base + t * 128;
            float4 v = x4[i];
            reinterpret_cast<uint2*>(g_xh)[i] =
                make_uint2(pack_h2(__float2half(v.x), __float2half(v.y)),
                           pack_h2(__float2half(v.z), __float2half(v.w)));
        }
        __threadfence();
        __syncthreads();
        if (tid == 0) atomicAdd(&g_done, 1u);
        return;
    }

    // ================= path 2: rotate via HMMA =================
    if (bid < N_PREP) {
        uint32_t sA[2] = {sm0, sm0 + 16384};
        uint32_t sB[2] = {sm0 + 32768, sm0 + 49152};

        int b = bid - N_CVT;                // 0..191
        int o0 = (b >> 3) * 128;            // 24 o-tiles
        int r  = b & 7;
        int wid = tid >> 5, lane = tid & 31;

        // load W tile [128 x 128] fp32 -> fp16, swizzled (half2 units)
        for (int u = tid; u < 128 * 64; u += 128) {
            int row = u >> 6;
            int col = (u & 63) * 2;
            const float2 w = *reinterpret_cast<const float2*>(
                W + (size_t)(o0 + row) * 1024 + r * 128 + col);
            int arr = col >> 6, c0 = col & 63;
            uint32_t dst = sA[arr] + swz(row, c0 >> 3) + (c0 & 7) * 2;
            asm volatile("st.shared.b32 [%0], %1;" :: "r"(dst),
                         "r"(pack_h2(__float2half(w.x), __float2half(w.y))) : "memory");
        }

        // load R^T: B[j][i] = R[i][j] (i lane-fastest: conflict-free smem)
        const float* R = ((o0 < 1024) ? qR : (o0 < 2048) ? kR : vR) + (size_t)r * 16384;
        for (int u = tid; u < 128 * 128; u += 128) {
            int i = u & 127;
            int j = u >> 7;
            __half h = __float2half(R[i * 128 + j]);
            int arr = i >> 6, c0 = i & 63;
            uint32_t dst = sB[arr] + swz(j, c0 >> 3) + (c0 & 7) * 2;
            uint16_t hb = *reinterpret_cast<uint16_t*>(&h);
            asm volatile("st.shared.b16 [%0], %1;" :: "r"(dst), "h"(hb) : "memory");
        }
        __syncthreads();

        // 4 warps 2(M) x 2(N); warp tile 64x64
        int wm = (wid & 1) * 64;
        int wn = (wid >> 1) * 64;
        int a_r    = lane & 15;
        int a_half = lane >> 4;
        int b_r    = ((lane >> 4) << 3) | (lane & 7);
        int b_half = (lane >> 3) & 1;

        float acc[4][8][4];
#pragma unroll
        for (int i = 0; i < 4; i++)
#pragma unroll
            for (int j = 0; j < 8; j++)
#pragma unroll
                for (int q = 0; q < 4; q++) acc[i][j][q] = 0.0f;

#pragma unroll
        for (int arr = 0; arr < 2; arr++) {
#pragma unroll
            for (int kk = 0; kk < 4; kk++) {
                int kb = kk * 2;
                uint32_t af[4][4], bfr[4][4];
#pragma unroll
                for (int mt = 0; mt < 4; mt++)
                    ldsm4(af[mt], sA[arr] + swz(wm + mt * 16 + a_r, kb + a_half));
#pragma unroll
                for (int nt = 0; nt < 4; nt++)
                    ldsm4(bfr[nt], sB[arr] + swz(wn + nt * 16 + b_r, kb + b_half));
#pragma unroll
                for (int mt = 0; mt < 4; mt++)
#pragma unroll
                    for (int n8 = 0; n8 < 8; n8++)
                        mma_f16(acc[mt][n8], af[mt], &bfr[n8 >> 1][(n8 & 1) * 2]);
            }
        }

        // store filt tile fp16
        int cr = lane >> 2, cc = (lane & 3) * 2;
#pragma unroll
        for (int mt = 0; mt < 4; mt++) {
#pragma unroll
            for (int n8 = 0; n8 < 8; n8++) {
                int col = wn + n8 * 8 + cc;
                int row0 = o0 + wm + mt * 16 + cr;
                __half2 v0 = __floats2half2_rn(acc[mt][n8][0], acc[mt][n8][1]);
                __half2 v1 = __floats2half2_rn(acc[mt][n8][2], acc[mt][n8][3]);
                *reinterpret_cast<__half2*>(g_fh + (size_t)row0 * 1024 + r * 128 + col) = v0;
                *reinterpret_cast<__half2*>(g_fh + (size_t)(row0 + 8) * 1024 + r * 128 + col) = v1;
            }
        }
        __threadfence();
        __syncthreads();
        if (tid == 0) atomicAdd(&g_done, 1u);
        return;
    }

    // ================= path 3: GEMM (gated) =================
    if (tid == 0) {
        while (atomicAdd(&g_done, 0u) < (unsigned)N_PREP) __nanosleep(64);
        __threadfence();
    }
    __syncthreads();

    int b = bid - N_PREP;
    int m0 = (b & 63) * BM;            // m fast-varying: B tile L2 reuse
    int n0 = (b >> 6) * BN;

    int wid = tid >> 5, lane = tid & 31;
    int wm = (wid & 1) * 64;
    int wn = (wid >> 1) * 64;

    int a_r    = lane & 15;
    int a_half = lane >> 4;
    int b_r    = ((lane >> 4) << 3) | (lane & 7);
    int b_half = (lane >> 3) & 1;

    float acc[4][8][4];
#pragma unroll
    for (int i = 0; i < 4; i++)
#pragma unroll
        for (int j = 0; j < 8; j++)
#pragma unroll
            for (int q = 0; q < 4; q++) acc[i][j][q] = 0.0f;

    load_stage(sm0, m0, n0, 0, tid); cp_commit();
    load_stage(sm0 + STAGE_BYTES, m0, n0, BK, tid); cp_commit();

    uint32_t af[2][4][4];
    uint32_t bf[2][4][4];

    for (int s = 0; s < NCHUNKS; s++) {
        if (s < NCHUNKS - 1) cp_wait1(); else cp_wait0();
        __syncthreads();

        uint32_t sb = sm0 + (s % 3) * STAGE_BYTES;
        uint32_t sA = sb, sB = sb + 16384;

#pragma unroll
        for (int mt = 0; mt < 4; mt++)
            ldsm4(af[0][mt], sA + swz(wm + mt * 16 + a_r, a_half));
#pragma unroll
        for (int nt = 0; nt < 4; nt++)
            ldsm4(bf[0][nt], sB + swz(wn + nt * 16 + b_r, b_half));

        if (s + 2 < NCHUNKS) {
            load_stage(sm0 + ((s + 2) % 3) * STAGE_BYTES, m0, n0, (s + 2) * BK, tid);
            cp_commit();
        }

#pragma unroll
        for (int kk = 0; kk < 4; kk++) {
            int cur = kk & 1, nxt = cur ^ 1;
            if (kk < 3) {
                int kb = (kk + 1) * 2;
#pragma unroll
                for (int mt = 0; mt < 4; mt++)
                    ldsm4(af[nxt][mt], sA + swz(wm + mt * 16 + a_r, kb + a_half));
#pragma unroll
                for (int nt = 0; nt < 4; nt++)
                    ldsm4(bf[nxt][nt], sB + swz(wn + nt * 16 + b_r, kb + b_half));
            }
#pragma unroll
            for (int mt = 0; mt < 4; mt++)
#pragma unroll
                for (int n8 = 0; n8 < 8; n8++)
                    mma_f16(acc[mt][n8], af[cur][mt], &bf[cur][n8 >> 1][(n8 & 1) * 2]);
        }
    }

    int cr = lane >> 2, cc = (lane & 3) * 2;
#pragma unroll
    for (int mt = 0; mt < 4; mt++) {
#pragma unroll
        for (int n8 = 0; n8 < 8; n8++) {
            int col = n0 + wn + n8 * 8 + cc;
            float b0 = __ldg(bias + col), b1 = __ldg(bias + col + 1);
            int row0 = m0 + wm + mt * 16 + cr;
            float2 v0 = make_float2(acc[mt][n8][0] + b0, acc[mt][n8][1] + b1);
            float2 v1 = make_float2(acc[mt][n8][2] + b0, acc[mt][n8][3] + b1);
            *reinterpret_cast<float2*>(out + (size_t)row0 * 3072 + col) = v0;
            *reinterpret_cast<float2*>(out + (size_t)(row0 + 8) * 3072 + col) = v1;
        }
    }

    // reset counters for next graph replay: last gemm block to finish resets
    __syncthreads();
    if (tid == 0) {
        unsigned p = atomicAdd(&g_passed, 1u) + 1u;
        if (p == (unsigned)N_GEMM) {
            atomicExch(&g_done, 0u);
            atomicExch(&g_passed, 0u);
        }
    }
}

// ==================== host ====================
extern "C" void kernel_launch(void* const* d_in, const int* in_sizes, int n_in,
                              void* d_out, int out_size) {
    const float* attn = (const float*)d_in[0];   // [3072, 1024]
    const float* bias = (const float*)d_in[1];   // [3072]
    const float* x    = (const float*)d_in[2];   // [4, 2048, 1024]
    const float* qR   = (const float*)d_in[3];   // [8, 128, 128]
    const float* kR   = (const float*)d_in[4];
    const float* vR   = (const float*)d_in[5];
    float* out = (float*)d_out;                  // [8192, 3072]

    cudaFuncSetAttribute(fused_kernel, cudaFuncAttributeMaxDynamicSharedMemorySize, SMEM_SIZE);
    fused_kernel<<<GRID, 128, SMEM_SIZE>>>(reinterpret_cast<const float4*>(x),
                                           attn, qR, kR, vR, bias, out);
}

// round 16
// speedup vs baseline: 1.0655x; 1.0655x over previous
#include <cuda_runtime.h>
#include <cuda_fp16.h>
#include <cstdint>

#define DINLINE __device__ __forceinline__

// ---------------- device scratch (no dynamic alloc allowed) ----------------
static __device__ __align__(16) __half g_xh[8192 * 1024];
static __device__ __align__(16) __half g_fh[3072 * 1024];

static constexpr int N_TILES = 1536;          // 64 m-tiles x 24 n-tiles
static constexpr int N_PERS  = 296;           // persistent gemm blocks (2/SM x 148)
static __device__ unsigned g_tile = N_PERS;   // next tile to claim
static __device__ unsigned g_fin  = 0;        // finished blocks (for replay reset)

// ---------------- portable PTX helpers (sm_80-class ISA only) ----------------
DINLINE uint32_t smem_u32(const void* p) {
    uint32_t a;
    asm("{ .reg .u64 t; cvta.to.shared.u64 t, %1; cvt.u32.u64 %0, t; }" : "=r"(a) : "l"(p));
    return a;
}
DINLINE void cp_async16(uint32_t dst, const void* src) {
    asm volatile("cp.async.cg.shared.global [%0], [%1], 16;" :: "r"(dst), "l"(src) : "memory");
}
DINLINE void cp_commit() { asm volatile("cp.async.commit_group;" ::: "memory"); }
DINLINE void cp_wait1() { asm volatile("cp.async.wait_group 1;" ::: "memory"); }

DINLINE void ldsm4(uint32_t* r, uint32_t addr) {
    asm volatile("ldmatrix.sync.aligned.m8n8.x4.shared.b16 {%0,%1,%2,%3}, [%4];"
                 : "=r"(r[0]), "=r"(r[1]), "=r"(r[2]), "=r"(r[3]) : "r"(addr));
}
DINLINE void mma_f16(float* c, const uint32_t* a, const uint32_t* b) {
    asm volatile(
        "mma.sync.aligned.m16n8k16.row.col.f32.f16.f16.f32 "
        "{%0,%1,%2,%3}, {%4,%5,%6,%7}, {%8,%9}, {%0,%1,%2,%3};"
        : "+f"(c[0]), "+f"(c[1]), "+f"(c[2]), "+f"(c[3])
        : "r"(a[0]), "r"(a[1]), "r"(a[2]), "r"(a[3]), "r"(b[0]), "r"(b[1]));
}

DINLINE uint32_t pack_h2(__half a, __half b) {
    __half2 t = __halves2half2(a, b);
    return *reinterpret_cast<uint32_t*>(&t);
}

// XOR swizzle on 128B rows: 16B-chunk c' = c ^ (row & 7)
DINLINE uint32_t swz(int row, int chunk) {
    return (uint32_t)(row * 128 + (chunk ^ (row & 7)) * 16);
}

// ==================== kernel 1: merged prologue (R14, proven) ====================
// blocks [0, 1024):     convert x -> fp16 (8 float4/thread)
// blocks [1024, 1216):  rotate W -> filt via HMMA (fp16 inputs, fp32 acc)
__global__ void __launch_bounds__(256, 2) prep_kernel(
    const float4* __restrict__ x4, const float* __restrict__ W,
    const float* __restrict__ qR, const float* __restrict__ kR,
    const float* __restrict__ vR) {
    if (blockIdx.x < 1024) {
        int base = blockIdx.x * 2048 + threadIdx.x;
#pragma unroll
        for (int t = 0; t < 8; t++) {
            int i = base + t * 256;
            float4 v = x4[i];
            reinterpret_cast<uint2*>(g_xh)[i] =
                make_uint2(pack_h2(__float2half(v.x), __float2half(v.y)),
                           pack_h2(__float2half(v.z), __float2half(v.w)));
        }
        return;
    }

    // ---------------- rotate via HMMA ----------------
    extern __shared__ __align__(128) char smem[];
    uint32_t sm0 = smem_u32(smem);
    uint32_t sA[2] = {sm0, sm0 + 16384};
    uint32_t sB[2] = {sm0 + 32768, sm0 + 49152};

    int b = blockIdx.x - 1024;          // 0..191
    int o0 = (b >> 3) * 128;            // 24 o-tiles
    int r  = b & 7;
    int tid = threadIdx.x;
    int wid = tid >> 5, lane = tid & 31;

    // load W tile [128 x 128] fp32 -> fp16, swizzled
    for (int u = tid; u < 128 * 64; u += 256) {
        int row = u >> 6;
        int col = (u & 63) * 2;
        const float2 w = *reinterpret_cast<const float2*>(
            W + (size_t)(o0 + row) * 1024 + r * 128 + col);
        int arr = col >> 6, c0 = col & 63;
        uint32_t dst = sA[arr] + swz(row, c0 >> 3) + (c0 & 7) * 2;
        asm volatile("st.shared.b32 [%0], %1;" :: "r"(dst),
                     "r"(pack_h2(__float2half(w.x), __float2half(w.y))) : "memory");
    }

    // load R^T: B[j][i] = R[i][j]
    const float* R = ((o0 < 1024) ? qR : (o0 < 2048) ? kR : vR) + (size_t)r * 16384;
    for (int u = tid; u < 128 * 128; u += 256) {
        int i = u & 127;
        int j = u >> 7;
        __half h = __float2half(R[i * 128 + j]);
        int arr = i >> 6, c0 = i & 63;
        uint32_t dst = sB[arr] + swz(j, c0 >> 3) + (c0 & 7) * 2;
        uint16_t hb = *reinterpret_cast<uint16_t*>(&h);
        asm volatile("st.shared.b16 [%0], %1;" :: "r"(dst), "h"(hb) : "memory");
    }
    __syncthreads();

    // 8 warps: 2(M) x 4(N); warp tile 64 x 32
    int wm = (wid & 1) * 64;
    int wn = (wid >> 1) * 32;
    int a_r    = lane & 15;
    int a_half = lane >> 4;
    int b_r    = ((lane >> 4) << 3) | (lane & 7);
    int b_half = (lane >> 3) & 1;

    float acc[4][4][4];
#pragma unroll
    for (int i = 0; i < 4; i++)
#pragma unroll
        for (int j = 0; j < 4; j++)
#pragma unroll
            for (int q = 0; q < 4; q++) acc[i][j][q] = 0.0f;

#pragma unroll
    for (int arr = 0; arr < 2; arr++) {
#pragma unroll
        for (int kk = 0; kk < 4; kk++) {
            int kb = kk * 2;
            uint32_t af[4][4], bfr[2][4];
#pragma unroll
            for (int mt = 0; mt < 4; mt++)
                ldsm4(af[mt], sA[arr] + swz(wm + mt * 16 + a_r, kb + a_half));
#pragma unroll
            for (int nt = 0; nt < 2; nt++)
                ldsm4(bfr[nt], sB[arr] + swz(wn + nt * 16 + b_r, kb + b_half));
#pragma unroll
            for (int mt = 0; mt < 4; mt++)
#pragma unroll
                for (int n8 = 0; n8 < 4; n8++)
                    mma_f16(acc[mt][n8], af[mt], &bfr[n8 >> 1][(n8 & 1) * 2]);
        }
    }

    int cr = lane >> 2, cc = (lane & 3) * 2;
#pragma unroll
    for (int mt = 0; mt < 4; mt++) {
#pragma unroll
        for (int n8 = 0; n8 < 4; n8++) {
            int col = wn + n8 * 8 + cc;
            int row0 = o0 + wm + mt * 16 + cr;
            __half2 v0 = __floats2half2_rn(acc[mt][n8][0], acc[mt][n8][1]);
            __half2 v1 = __floats2half2_rn(acc[mt][n8][2], acc[mt][n8][3]);
            *reinterpret_cast<__half2*>(g_fh + (size_t)row0 * 1024 + r * 128 + col) = v0;
            *reinterpret_cast<__half2*>(g_fh + (size_t)(row0 + 8) * 1024 + r * 128 + col) = v1;
        }
    }
}

// ==================== kernel 2: persistent HMMA GEMM ====================
// out[8192,3072] = Xh*Fh^T + bias
// 296 persistent blocks; dynamic tile claiming; seamless 3-slot ring across
// tiles: stages 14-15 of tile t load chunks 0-1 of tile t+1; epilogue overlaps
// the next tile's loads. One commit per stage (possibly empty) keeps
// cp.async.wait_group 1 semantics uniform (in-order group completion).
static constexpr int BM = 128, BN = 128, BK = 64;
static constexpr int NCHUNKS = 1024 / BK;       // 16
static constexpr int STAGE_BYTES = 32768;
static constexpr int SMEM_SIZE = 3 * STAGE_BYTES;   // 96KB -> 2 CTAs/SM

DINLINE void load_stage(uint32_t sbase, int m0, int n0, int k0, int tid) {
#pragma unroll
    for (int t = 0; t < 16; t++) {
        int idx = tid + t * 128;
        int arr = idx >> 10;         // 0:A 1:B
        int rem = idx & 1023;
        int row = rem >> 3, chunk = rem & 7;
        const __half* src = (arr == 0)
            ? g_xh + (size_t)(m0 + row) * 1024 + k0 + chunk * 8
            : g_fh + (size_t)(n0 + row) * 1024 + k0 + chunk * 8;
        cp_async16(sbase + arr * 16384 + swz(row, chunk), src);
    }
}

__global__ void __launch_bounds__(128, 2) gemm_kernel(
    const float* __restrict__ bias, float* __restrict__ out) {
    extern __shared__ __align__(128) char smem[];
    __shared__ unsigned s_nxt;
    uint32_t sm0 = smem_u32(smem);

    int tid = threadIdx.x;
    int wid = tid >> 5, lane = tid & 31;
    int wm = (wid & 1) * 64;
    int wn = (wid >> 1) * 64;

    int a_r    = lane & 15;
    int a_half = lane >> 4;
    int b_r    = ((lane >> 4) << 3) | (lane & 7);
    int b_half = (lane >> 3) & 1;

    int cur = blockIdx.x;                        // first tile = bid (no atomic)
    int m0 = (cur & 63) * BM;
    int n0 = (cur >> 6) * BN;

    float acc[4][8][4];
#pragma unroll
    for (int i = 0; i < 4; i++)
#pragma unroll
        for (int j = 0; j < 8; j++)
#pragma unroll
            for (int q = 0; q < 4; q++) acc[i][j][q] = 0.0f;

    // prologue: chunks 0,1 of first tile into ring slots 0,1
    load_stage(sm0, m0, n0, 0, tid); cp_commit();
    load_stage(sm0 + STAGE_BYTES, m0, n0, BK, tid); cp_commit();
    int ring = 0;                                // ring slot of current chunk

    uint32_t af[2][4][4];
    uint32_t bf[2][4][4];

    for (;;) {
#pragma unroll 1
        for (int s = 0; s < NCHUNKS; s++) {
            cp_wait1();
            __syncthreads();

            uint32_t sb = sm0 + ring * STAGE_BYTES;
            uint32_t sA = sb, sB = sb + 16384;

            // boundary fill: fragments for k16-step 0 of this chunk
#pragma unroll
            for (int mt = 0; mt < 4; mt++)
                ldsm4(af[0][mt], sA + swz(wm + mt * 16 + a_r, a_half));
#pragma unroll
            for (int nt = 0; nt < 4; nt++)
                ldsm4(bf[0][nt], sB + swz(wn + nt * 16 + b_r, b_half));

            // claim next tile early; visible to all after s==13's barrier
            if (s == 12 && tid == 0) s_nxt = atomicAdd(&g_tile, 1u);

            // lookahead load into slot ring+2 (one commit per stage, maybe empty)
            int slot = ring + 2; if (slot >= 3) slot -= 3;
            if (s < NCHUNKS - 2) {
                load_stage(sm0 + slot * STAGE_BYTES, m0, n0, (s + 2) * BK, tid);
            } else {
                int nt = (int)s_nxt;             // written s==12, fenced by s==13 bar
                if (nt < N_TILES) {
                    int nm0 = (nt & 63) * BM, nn0 = (nt >> 6) * BN;
                    load_stage(sm0 + slot * STAGE_BYTES, nm0, nn0,
                               (s - (NCHUNKS - 2)) * BK, tid);
                }
            }
            cp_commit();

#pragma unroll
            for (int kk = 0; kk < 4; kk++) {
                int cb = kk & 1, nb = cb ^ 1;
                if (kk < 3) {
                    int kb = (kk + 1) * 2;
#pragma unroll
                    for (int mt = 0; mt < 4; mt++)
                        ldsm4(af[nb][mt], sA + swz(wm + mt * 16 + a_r, kb + a_half));
#pragma unroll
                    for (int nt = 0; nt < 4; nt++)
                        ldsm4(bf[nb][nt], sB + swz(wn + nt * 16 + b_r, kb + b_half));
                }
#pragma unroll
                for (int mt = 0; mt < 4; mt++)
#pragma unroll
                    for (int n8 = 0; n8 < 8; n8++)
                        mma_f16(acc[mt][n8], af[cb][mt], &bf[cb][n8 >> 1][(n8 & 1) * 2]);
            }

            ring++; if (ring >= 3) ring = 0;
        }

        // epilogue (overlaps next tile's in-flight chunk 0/1 loads)
        int cr = lane >> 2, cc = (lane & 3) * 2;
#pragma unroll
        for (int mt = 0; mt < 4; mt++) {
#pragma unroll
            for (int n8 = 0; n8 < 8; n8++) {
                int col = n0 + wn + n8 * 8 + cc;
                float b0 = __ldg(bias + col), b1 = __ldg(bias + col + 1);
                int row0 = m0 + wm + mt * 16 + cr;
                float2 v0 = make_float2(acc[mt][n8][0] + b0, acc[mt][n8][1] + b1);
                float2 v1 = make_float2(acc[mt][n8][2] + b0, acc[mt][n8][3] + b1);
                *reinterpret_cast<float2*>(out + (size_t)row0 * 3072 + col) = v0;
                *reinterpret_cast<float2*>(out + (size_t)(row0 + 8) * 3072 + col) = v1;
            }
        }

        int nt = (int)s_nxt;
        if (nt >= N_TILES) break;
        cur = nt;
        m0 = (cur & 63) * BM;
        n0 = (cur >> 6) * BN;

#pragma unroll
        for (int i = 0; i < 4; i++)
#pragma unroll
            for (int j = 0; j < 8; j++)
#pragma unroll
                for (int q = 0; q < 4; q++) acc[i][j][q] = 0.0f;
    }

    // replay-safe counter reset: last of 296 blocks restores state
    __syncthreads();
    if (tid == 0) {
        unsigned f = atomicAdd(&g_fin, 1u) + 1u;
        if (f == (unsigned)N_PERS) {
            atomicExch(&g_tile, (unsigned)N_PERS);
            atomicExch(&g_fin, 0u);
        }
    }
}

// ==================== host ====================
extern "C" void kernel_launch(void* const* d_in, const int* in_sizes, int n_in,
                              void* d_out, int out_size) {
    const float* attn = (const float*)d_in[0];   // [3072, 1024]
    const float* bias = (const float*)d_in[1];   // [3072]
    const float* x    = (const float*)d_in[2];   // [4, 2048, 1024]
    const float* qR   = (const float*)d_in[3];   // [8, 128, 128]
    const float* kR   = (const float*)d_in[4];
    const float* vR   = (const float*)d_in[5];
    float* out = (float*)d_out;                  // [8192, 3072]

    cudaFuncSetAttribute(prep_kernel, cudaFuncAttributeMaxDynamicSharedMemorySize, 65536);
    prep_kernel<<<1024 + 192, 256, 65536>>>(reinterpret_cast<const float4*>(x),
                                            attn, qR, kR, vR);

    cudaFuncSetAttribute(gemm_kernel, cudaFuncAttributeMaxDynamicSharedMemorySize, SMEM_SIZE);
    gemm_kernel<<<N_PERS, 128, SMEM_SIZE>>>(bias, out);
}

// round 17
// speedup vs baseline: 1.0869x; 1.0201x over previous
#include <cuda_runtime.h>
#include <cuda_fp16.h>
#include <cstdint>

#define DINLINE __device__ __forceinline__

// ---------------- device scratch (no dynamic alloc allowed) ----------------
static __device__ __align__(16) __half g_xh[8192 * 1024];
static __device__ __align__(16) __half g_fh[3072 * 1024];

// ---------------- portable PTX helpers (sm_80-class ISA only) ----------------
DINLINE uint32_t smem_u32(const void* p) {
    uint32_t a;
    asm("{ .reg .u64 t; cvta.to.shared.u64 t, %1; cvt.u32.u64 %0, t; }" : "=r"(a) : "l"(p));
    return a;
}
DINLINE void cp_async16(uint32_t dst, const void* src) {
    asm volatile("cp.async.cg.shared.global [%0], [%1], 16;" :: "r"(dst), "l"(src) : "memory");
}
DINLINE void cp_commit() { asm volatile("cp.async.commit_group;" ::: "memory"); }
DINLINE void cp_wait0() { asm volatile("cp.async.wait_group 0;" ::: "memory"); }
DINLINE void cp_wait1() { asm volatile("cp.async.wait_group 1;" ::: "memory"); }

DINLINE void ldsm4(uint32_t* r, uint32_t addr) {
    asm volatile("ldmatrix.sync.aligned.m8n8.x4.shared.b16 {%0,%1,%2,%3}, [%4];"
                 : "=r"(r[0]), "=r"(r[1]), "=r"(r[2]), "=r"(r[3]) : "r"(addr));
}
DINLINE void mma_f16(float* c, const uint32_t* a, const uint32_t* b) {
    asm volatile(
        "mma.sync.aligned.m16n8k16.row.col.f32.f16.f16.f32 "
        "{%0,%1,%2,%3}, {%4,%5,%6,%7}, {%8,%9}, {%0,%1,%2,%3};"
        : "+f"(c[0]), "+f"(c[1]), "+f"(c[2]), "+f"(c[3])
        : "r"(a[0]), "r"(a[1]), "r"(a[2]), "r"(a[3]), "r"(b[0]), "r"(b[1]));
}

DINLINE uint32_t pack_h2(__half a, __half b) {
    __half2 t = __halves2half2(a, b);
    return *reinterpret_cast<uint32_t*>(&t);
}

// XOR swizzle on 128B rows: 16B-chunk c' = c ^ (row & 7)
DINLINE uint32_t swz(int row, int chunk) {
    return (uint32_t)(row * 128 + (chunk ^ (row & 7)) * 16);
}

// ==================== kernel 1: merged prologue (R14, proven) ====================
// blocks [0, 1024):     convert x -> fp16 (8 float4/thread)
// blocks [1024, 1216):  rotate W -> filt via HMMA (fp16 inputs, fp32 acc)
__global__ void __launch_bounds__(256, 2) prep_kernel(
    const float4* __restrict__ x4, const float* __restrict__ W,
    const float* __restrict__ qR, const float* __restrict__ kR,
    const float* __restrict__ vR) {
    if (blockIdx.x < 1024) {
        int base = blockIdx.x * 2048 + threadIdx.x;
#pragma unroll
        for (int t = 0; t < 8; t++) {
            int i = base + t * 256;
            float4 v = x4[i];
            reinterpret_cast<uint2*>(g_xh)[i] =
                make_uint2(pack_h2(__float2half(v.x), __float2half(v.y)),
                           pack_h2(__float2half(v.z), __float2half(v.w)));
        }
        return;
    }

    // ---------------- rotate via HMMA ----------------
    extern __shared__ __align__(128) char smem[];
    uint32_t sm0 = smem_u32(smem);
    uint32_t sA[2] = {sm0, sm0 + 16384};
    uint32_t sB[2] = {sm0 + 32768, sm0 + 49152};

    int b = blockIdx.x - 1024;          // 0..191
    int o0 = (b >> 3) * 128;            // 24 o-tiles
    int r  = b & 7;
    int tid = threadIdx.x;
    int wid = tid >> 5, lane = tid & 31;

    // load W tile [128 x 128] fp32 -> fp16, swizzled
    for (int u = tid; u < 128 * 64; u += 256) {
        int row = u >> 6;
        int col = (u & 63) * 2;
        const float2 w = *reinterpret_cast<const float2*>(
            W + (size_t)(o0 + row) * 1024 + r * 128 + col);
        int arr = col >> 6, c0 = col & 63;
        uint32_t dst = sA[arr] + swz(row, c0 >> 3) + (c0 & 7) * 2;
        asm volatile("st.shared.b32 [%0], %1;" :: "r"(dst),
                     "r"(pack_h2(__float2half(w.x), __float2half(w.y))) : "memory");
    }

    // load R^T: B[j][i] = R[i][j]
    const float* R = ((o0 < 1024) ? qR : (o0 < 2048) ? kR : vR) + (size_t)r * 16384;
    for (int u = tid; u < 128 * 128; u += 256) {
        int i = u & 127;
        int j = u >> 7;
        __half h = __float2half(R[i * 128 + j]);
        int arr = i >> 6, c0 = i & 63;
        uint32_t dst = sB[arr] + swz(j, c0 >> 3) + (c0 & 7) * 2;
        uint16_t hb = *reinterpret_cast<uint16_t*>(&h);
        asm volatile("st.shared.b16 [%0], %1;" :: "r"(dst), "h"(hb) : "memory");
    }
    __syncthreads();

    // 8 warps: 2(M) x 4(N); warp tile 64 x 32
    int wm = (wid & 1) * 64;
    int wn = (wid >> 1) * 32;
    int a_r    = lane & 15;
    int a_half = lane >> 4;
    int b_r    = ((lane >> 4) << 3) | (lane & 7);
    int b_half = (lane >> 3) & 1;

    float acc[4][4][4];
#pragma unroll
    for (int i = 0; i < 4; i++)
#pragma unroll
        for (int j = 0; j < 4; j++)
#pragma unroll
            for (int q = 0; q < 4; q++) acc[i][j][q] = 0.0f;

#pragma unroll
    for (int arr = 0; arr < 2; arr++) {
#pragma unroll
        for (int kk = 0; kk < 4; kk++) {
            int kb = kk * 2;
            uint32_t af[4][4], bfr[2][4];
#pragma unroll
            for (int mt = 0; mt < 4; mt++)
                ldsm4(af[mt], sA[arr] + swz(wm + mt * 16 + a_r, kb + a_half));
#pragma unroll
            for (int nt = 0; nt < 2; nt++)
                ldsm4(bfr[nt], sB[arr] + swz(wn + nt * 16 + b_r, kb + b_half));
#pragma unroll
            for (int mt = 0; mt < 4; mt++)
#pragma unroll
                for (int n8 = 0; n8 < 4; n8++)
                    mma_f16(acc[mt][n8], af[mt], &bfr[n8 >> 1][(n8 & 1) * 2]);
        }
    }

    int cr = lane >> 2, cc = (lane & 3) * 2;
#pragma unroll
    for (int mt = 0; mt < 4; mt++) {
#pragma unroll
        for (int n8 = 0; n8 < 4; n8++) {
            int col = wn + n8 * 8 + cc;
            int row0 = o0 + wm + mt * 16 + cr;
            __half2 v0 = __floats2half2_rn(acc[mt][n8][0], acc[mt][n8][1]);
            __half2 v1 = __floats2half2_rn(acc[mt][n8][2], acc[mt][n8][3]);
            *reinterpret_cast<__half2*>(g_fh + (size_t)row0 * 1024 + r * 128 + col) = v0;
            *reinterpret_cast<__half2*>(g_fh + (size_t)(row0 + 8) * 1024 + r * 128 + col) = v1;
        }
    }
}

// ==================== kernel 2: HMMA GEMM, register-diet ====================
// out[8192,3072] = Xh*Fh^T + bias
// R12 config (best measured: BM=128, BN=128, BK=64, 3-stage wait1 pipeline,
// 128 threads, 2 CTAs/SM, 64x64 warp tile) with SINGLE-buffered fragments:
// acc 128 + frags 32 + addressing ~40 => ~210 regs, well under the 256 cap,
// eliminating the spills suspected at regs=254 (L1 41% unexplained traffic).
// ldsm->mma RAW bubbles are covered by the sibling CTA's warp on each SMSP.
static constexpr int BM = 128, BN = 128, BK = 64;
static constexpr int NCHUNKS = 1024 / BK;       // 16
static constexpr int STAGE_BYTES = 32768;
static constexpr int SMEM_SIZE = 3 * STAGE_BYTES;   // 96KB -> 2 CTAs/SM

DINLINE void load_stage(uint32_t sbase, int m0, int n0, int k0, int tid) {
#pragma unroll
    for (int t = 0; t < 16; t++) {
        int idx = tid + t * 128;
        int arr = idx >> 10;         // 0:A 1:B
        int rem = idx & 1023;
        int row = rem >> 3, chunk = rem & 7;
        const __half* src = (arr == 0)
            ? g_xh + (size_t)(m0 + row) * 1024 + k0 + chunk * 8
            : g_fh + (size_t)(n0 + row) * 1024 + k0 + chunk * 8;
        cp_async16(sbase + arr * 16384 + swz(row, chunk), src);
    }
}

__global__ void __launch_bounds__(128, 2) gemm_kernel(
    const float* __restrict__ bias, float* __restrict__ out) {
    extern __shared__ __align__(128) char smem[];
    uint32_t sm0 = smem_u32(smem);

    int tid = threadIdx.x;
    int wid = tid >> 5, lane = tid & 31;
    int wm = (wid & 1) * 64;
    int wn = (wid >> 1) * 64;
    int m0 = blockIdx.x * BM;
    int n0 = blockIdx.y * BN;

    int a_r    = lane & 15;
    int a_half = lane >> 4;
    int b_r    = ((lane >> 4) << 3) | (lane & 7);
    int b_half = (lane >> 3) & 1;

    float acc[4][8][4];
#pragma unroll
    for (int i = 0; i < 4; i++)
#pragma unroll
        for (int j = 0; j < 8; j++)
#pragma unroll
            for (int q = 0; q < 4; q++) acc[i][j][q] = 0.0f;

    load_stage(sm0, m0, n0, 0, tid); cp_commit();
    load_stage(sm0 + STAGE_BYTES, m0, n0, BK, tid); cp_commit();

    uint32_t af[4][4];   // single-buffered fragments
    uint32_t bf[4][4];

    for (int s = 0; s < NCHUNKS; s++) {
        if (s < NCHUNKS - 1) cp_wait1(); else cp_wait0();
        __syncthreads();

        uint32_t sb = sm0 + (s % 3) * STAGE_BYTES;
        uint32_t sA = sb, sB = sb + 16384;

        // kk = 0: ldsm, then prefetch s+2 (off the critical path), then mma
#pragma unroll
        for (int mt = 0; mt < 4; mt++)
            ldsm4(af[mt], sA + swz(wm + mt * 16 + a_r, a_half));
#pragma unroll
        for (int nt = 0; nt < 4; nt++)
            ldsm4(bf[nt], sB + swz(wn + nt * 16 + b_r, b_half));

        if (s + 2 < NCHUNKS) {
            load_stage(sm0 + ((s + 2) % 3) * STAGE_BYTES, m0, n0, (s + 2) * BK, tid);
            cp_commit();
        }

#pragma unroll
        for (int mt = 0; mt < 4; mt++)
#pragma unroll
            for (int n8 = 0; n8 < 8; n8++)
                mma_f16(acc[mt][n8], af[mt], &bf[n8 >> 1][(n8 & 1) * 2]);

        // kk = 1..3
#pragma unroll
        for (int kk = 1; kk < 4; kk++) {
            int kb = kk * 2;
#pragma unroll
            for (int mt = 0; mt < 4; mt++)
                ldsm4(af[mt], sA + swz(wm + mt * 16 + a_r, kb + a_half));
#pragma unroll
            for (int nt = 0; nt < 4; nt++)
                ldsm4(bf[nt], sB + swz(wn + nt * 16 + b_r, kb + b_half));
#pragma unroll
            for (int mt = 0; mt < 4; mt++)
#pragma unroll
                for (int n8 = 0; n8 < 8; n8++)
                    mma_f16(acc[mt][n8], af[mt], &bf[n8 >> 1][(n8 & 1) * 2]);
        }
    }

    // epilogue: C frag lane mapping: rows l/4, l/4+8; cols (l%4)*2, +1
    int cr = lane >> 2, cc = (lane & 3) * 2;
#pragma unroll
    for (int mt = 0; mt < 4; mt++) {
#pragma unroll
        for (int n8 = 0; n8 < 8; n8++) {
            int col = n0 + wn + n8 * 8 + cc;
            float b0 = __ldg(bias + col), b1 = __ldg(bias + col + 1);
            int row0 = m0 + wm + mt * 16 + cr;
            float2 v0 = make_float2(acc[mt][n8][0] + b0, acc[mt][n8][1] + b1);
            float2 v1 = make_float2(acc[mt][n8][2] + b0, acc[mt][n8][3] + b1);
            *reinterpret_cast<float2*>(out + (size_t)row0 * 3072 + col) = v0;
            *reinterpret_cast<float2*>(out + (size_t)(row0 + 8) * 3072 + col) = v1;
        }
    }
}

// ==================== host ====================
extern "C" void kernel_launch(void* const* d_in, const int* in_sizes, int n_in,
                              void* d_out, int out_size) {
    const float* attn = (const float*)d_in[0];   // [3072, 1024]
    const float* bias = (const float*)d_in[1];   // [3072]
    const float* x    = (const float*)d_in[2];   // [4, 2048, 1024]
    const float* qR   = (const float*)d_in[3];   // [8, 128, 128]
    const float* kR   = (const float*)d_in[4];
    const float* vR   = (const float*)d_in[5];
    float* out = (float*)d_out;                  // [8192, 3072]

    cudaFuncSetAttribute(prep_kernel, cudaFuncAttributeMaxDynamicSharedMemorySize, 65536);
    prep_kernel<<<1024 + 192, 256, 65536>>>(reinterpret_cast<const float4*>(x),
                                            attn, qR, kR, vR);

    cudaFuncSetAttribute(gemm_kernel, cudaFuncAttributeMaxDynamicSharedMemorySize, SMEM_SIZE);
    gemm_kernel<<<dim3(64, 24), 128, SMEM_SIZE>>>(bias, out);
}